// round 12
// baseline (speedup 1.0000x reference)
#include <cuda_runtime.h>
#include <cuda_bf16.h>
#include <cstdint>
#include <math.h>

// Problem constants
#define BB   2
#define SS   2048
#define DD   768
#define HH   12
#define HDIM 64
#define HALFW 64
#define NEGV -1000000000.0f

// ---------------------------------------------------------------------------
// Scratch (no cudaMalloc allowed)
// ---------------------------------------------------------------------------
__device__ __nv_bfloat16 g_qkvh[BB * SS * 3 * DD];   // qkv hi split (written by GEMM)
__device__ __nv_bfloat16 g_qkvl[BB * SS * 3 * DD];   // qkv lo split
__device__ __nv_bfloat16 g_xhi[BB * SS * DD];        // x split
__device__ __nv_bfloat16 g_xlo[BB * SS * DD];
__device__ __nv_bfloat16 g_wqh[3 * DD * DD];         // Wqkv^T split (2304 x 768)
__device__ __nv_bfloat16 g_wql[3 * DD * DD];
__device__ __nv_bfloat16 g_woh[DD * DD];             // Wo^T split (768 x 768)
__device__ __nv_bfloat16 g_wol[DD * DD];
__device__ __nv_bfloat16 g_ahi[BB * SS * DD];        // attn out split (written by attn)
__device__ __nv_bfloat16 g_alo[BB * SS * DD];

// ---------------------------------------------------------------------------
// Common helpers
// ---------------------------------------------------------------------------
__device__ __forceinline__ uint32_t smem_u32(const void* p) {
    uint32_t a;
    asm("{ .reg .u64 t; cvta.to.shared.u64 t, %1; cvt.u32.u64 %0, t; }"
        : "=r"(a) : "l"(p));
    return a;
}

__device__ __forceinline__ void cp_async16(uint32_t dst, const void* src) {
    asm volatile("cp.async.cg.shared.global [%0], [%1], 16;" :: "r"(dst), "l"(src));
}
// zero-fill variant: srcsize==0 -> 16B of zeros (src not read)
__device__ __forceinline__ void cp_async16z(uint32_t dst, const void* src, uint32_t srcsize) {
    asm volatile("cp.async.cg.shared.global [%0], [%1], 16, %2;"
                 :: "r"(dst), "l"(src), "r"(srcsize));
}
#define CP_COMMIT() asm volatile("cp.async.commit_group;" ::: "memory")
#define CP_WAIT1()  asm volatile("cp.async.wait_group 1;" ::: "memory")
#define CP_WAIT0()  asm volatile("cp.async.wait_group 0;" ::: "memory")

#define LDSM_X4(r0, r1, r2, r3, addr) \
    asm volatile("ldmatrix.sync.aligned.m8n8.x4.shared.b16 {%0,%1,%2,%3}, [%4];" \
                 : "=r"(r0), "=r"(r1), "=r"(r2), "=r"(r3) : "r"(addr))
#define LDSM_X2(r0, r1, addr) \
    asm volatile("ldmatrix.sync.aligned.m8n8.x2.shared.b16 {%0,%1}, [%2];" \
                 : "=r"(r0), "=r"(r1) : "r"(addr))
#define LDSM_X2T(r0, r1, addr) \
    asm volatile("ldmatrix.sync.aligned.m8n8.x2.trans.shared.b16 {%0,%1}, [%2];" \
                 : "=r"(r0), "=r"(r1) : "r"(addr))

__device__ __forceinline__ void mma16816(float* c, const uint32_t* a, const uint32_t* b)
{
    asm volatile(
        "mma.sync.aligned.m16n8k16.row.col.f32.bf16.bf16.f32 "
        "{%0,%1,%2,%3}, {%4,%5,%6,%7}, {%8,%9}, {%0,%1,%2,%3};"
        : "+f"(c[0]), "+f"(c[1]), "+f"(c[2]), "+f"(c[3])
        : "r"(a[0]), "r"(a[1]), "r"(a[2]), "r"(a[3]), "r"(b[0]), "r"(b[1]));
}

__device__ __forceinline__ void split2(float a, float b, uint32_t& hi, uint32_t& lo)
{
    __nv_bfloat16 ha = __float2bfloat16(a), hb = __float2bfloat16(b);
    __nv_bfloat16 la = __float2bfloat16(a - __bfloat162float(ha));
    __nv_bfloat16 lb = __float2bfloat16(b - __bfloat162float(hb));
    hi = ((uint32_t)__bfloat16_as_ushort(hb) << 16) | (uint32_t)__bfloat16_as_ushort(ha);
    lo = ((uint32_t)__bfloat16_as_ushort(lb) << 16) | (uint32_t)__bfloat16_as_ushort(la);
}

// ---------------------------------------------------------------------------
// Split / transpose-split conversion kernels
// ---------------------------------------------------------------------------
__global__ __launch_bounds__(256) void split_kernel(
    const float* __restrict__ in, __nv_bfloat16* __restrict__ hi,
    __nv_bfloat16* __restrict__ lo, int n)
{
    int i = blockIdx.x * 256 + threadIdx.x;
    if (i < n) {
        float v = in[i];
        __nv_bfloat16 h = __float2bfloat16(v);
        hi[i] = h;
        lo[i] = __float2bfloat16(v - __bfloat162float(h));
    }
}

__global__ __launch_bounds__(256) void splitT_kernel(
    const float* __restrict__ in, __nv_bfloat16* __restrict__ hiT,
    __nv_bfloat16* __restrict__ loT, int K, int N)
{
    __shared__ float t[32][33];
    const int k0 = blockIdx.y * 32, n0 = blockIdx.x * 32;
    const int tx = threadIdx.x, ty = threadIdx.y;   // 32 x 8
    #pragma unroll
    for (int i = 0; i < 32; i += 8)
        t[ty + i][tx] = in[(size_t)(k0 + ty + i) * N + n0 + tx];
    __syncthreads();
    #pragma unroll
    for (int i = 0; i < 32; i += 8) {
        float v = t[tx][ty + i];
        __nv_bfloat16 h = __float2bfloat16(v);
        size_t o = (size_t)(n0 + ty + i) * K + k0 + tx;
        hiT[o] = h;
        loT[o] = __float2bfloat16(v - __bfloat162float(h));
    }
}

// ---------------------------------------------------------------------------
// bf16x3 mma.sync GEMM (round-7 proven shape: BK=32, 2-stage cp.async).
// C[M,N] = A[M,K] @ Bt[N,K]^T, fp32 accumulate.
// SPLIT_OUT=false: write fp32 C.  SPLIT_OUT=true: write bf16 hi/lo split.
// ---------------------------------------------------------------------------
#define SMS 40
#define TILE_BYTES (128 * SMS * 2)
#define STAGE_BYTES (4 * TILE_BYTES)
#define GEMM_SMEM (2 * STAGE_BYTES)

template<bool SPLIT_OUT>
__global__ __launch_bounds__(256) void gemm_bf16x3_kernel(
    const __nv_bfloat16* __restrict__ Ahi, const __nv_bfloat16* __restrict__ Alo,
    const __nv_bfloat16* __restrict__ Bthi, const __nv_bfloat16* __restrict__ Btlo,
    float* __restrict__ C,
    __nv_bfloat16* __restrict__ Chi, __nv_bfloat16* __restrict__ Clo,
    int M, int N, int K)
{
    extern __shared__ __align__(128) char smem[];
    const uint32_t smem_base = smem_u32(smem);

    const int tid = threadIdx.x;
    const int wid = tid >> 5, lane = tid & 31;
    const int g = lane >> 2, tg = lane & 3;
    const int wm = wid >> 2, wn = wid & 3;
    const int mbase = wm * 64, nbase = wn * 32;
    const int bm = blockIdx.y * 128, bn = blockIdx.x * 128;

    const __nv_bfloat16* srcs[4] = {
        Ahi + (size_t)bm * K, Alo + (size_t)bm * K,
        Bthi + (size_t)bn * K, Btlo + (size_t)bn * K };

    const int niter = K >> 5;
    const int lr0 = tid >> 2, lq = tid & 3;
    const uint32_t st_off = (uint32_t)(lr0 * SMS + lq * 8) * 2;

    const uint32_t a_lane = (uint32_t)((lane & 15) * (SMS * 2) + ((lane >> 4) << 4));
    const uint32_t b_lane = (uint32_t)((lane & 7) * (SMS * 2) + (((lane >> 3) & 1) << 4));

    float acc[4][4][4];
    #pragma unroll
    for (int i = 0; i < 4; i++)
        #pragma unroll
        for (int j = 0; j < 4; j++)
            #pragma unroll
            for (int c = 0; c < 4; c++) acc[i][j][c] = 0.f;

    #pragma unroll
    for (int p = 0; p < 2; p++) {
        if (p < niter) {
            const int k0 = p << 5;
            const uint32_t sb = smem_base + (uint32_t)p * STAGE_BYTES;
            #pragma unroll
            for (int t = 0; t < 4; t++) {
                const __nv_bfloat16* s = srcs[t] + k0 + lq * 8;
                uint32_t d = sb + (uint32_t)t * TILE_BYTES + st_off;
                cp_async16(d, s + (size_t)lr0 * K);
                cp_async16(d + 64 * SMS * 2, s + (size_t)(lr0 + 64) * K);
            }
        }
        CP_COMMIT();
    }

    for (int it = 0; it < niter; it++) {
        CP_WAIT1();
        __syncthreads();

        const uint32_t sb = smem_base + (uint32_t)(it & 1) * STAGE_BYTES;
        const uint32_t aAh = sb + a_lane;
        const uint32_t aAl = sb + TILE_BYTES + a_lane;
        const uint32_t aBh = sb + 2 * TILE_BYTES + b_lane;
        const uint32_t aBl = sb + 3 * TILE_BYTES + b_lane;

        #pragma unroll
        for (int kk = 0; kk < 32; kk += 16) {
            uint32_t ah[4][4], al[4][4], bh[4][2], bl[4][2];
            #pragma unroll
            for (int mt = 0; mt < 4; mt++) {
                const uint32_t ro = (uint32_t)((mbase + mt * 16) * (SMS * 2) + kk * 2);
                LDSM_X4(ah[mt][0], ah[mt][1], ah[mt][2], ah[mt][3], aAh + ro);
                LDSM_X4(al[mt][0], al[mt][1], al[mt][2], al[mt][3], aAl + ro);
            }
            #pragma unroll
            for (int nt = 0; nt < 4; nt++) {
                const uint32_t ro = (uint32_t)((nbase + nt * 8) * (SMS * 2) + kk * 2);
                LDSM_X2(bh[nt][0], bh[nt][1], aBh + ro);
                LDSM_X2(bl[nt][0], bl[nt][1], aBl + ro);
            }
            #pragma unroll
            for (int mt = 0; mt < 4; mt++)
                #pragma unroll
                for (int nt = 0; nt < 4; nt++)
                    mma16816(acc[mt][nt], ah[mt], bh[nt]);
            #pragma unroll
            for (int mt = 0; mt < 4; mt++)
                #pragma unroll
                for (int nt = 0; nt < 4; nt++)
                    mma16816(acc[mt][nt], ah[mt], bl[nt]);
            #pragma unroll
            for (int mt = 0; mt < 4; mt++)
                #pragma unroll
                for (int nt = 0; nt < 4; nt++)
                    mma16816(acc[mt][nt], al[mt], bh[nt]);
        }
        __syncthreads();

        const int nx = it + 2;
        if (nx < niter) {
            const int k0 = nx << 5;
            const uint32_t db = smem_base + (uint32_t)(nx & 1) * STAGE_BYTES;
            #pragma unroll
            for (int t = 0; t < 4; t++) {
                const __nv_bfloat16* s = srcs[t] + k0 + lq * 8;
                uint32_t d = db + (uint32_t)t * TILE_BYTES + st_off;
                cp_async16(d, s + (size_t)lr0 * K);
                cp_async16(d + 64 * SMS * 2, s + (size_t)(lr0 + 64) * K);
            }
        }
        CP_COMMIT();
    }

    #pragma unroll
    for (int mt = 0; mt < 4; mt++) {
        #pragma unroll
        for (int nt = 0; nt < 4; nt++) {
            const int row = bm + mbase + mt * 16 + g;
            const int col = bn + nbase + nt * 8 + tg * 2;
            if (SPLIT_OUT) {
                uint32_t hi, lo;
                size_t off = (size_t)row * N + col;
                split2(acc[mt][nt][0], acc[mt][nt][1], hi, lo);
                *(uint32_t*)(Chi + off) = hi;
                *(uint32_t*)(Clo + off) = lo;
                off += (size_t)8 * N;
                split2(acc[mt][nt][2], acc[mt][nt][3], hi, lo);
                *(uint32_t*)(Chi + off) = hi;
                *(uint32_t*)(Clo + off) = lo;
            } else {
                float2 v0; v0.x = acc[mt][nt][0]; v0.y = acc[mt][nt][1];
                float2 v1; v1.x = acc[mt][nt][2]; v1.y = acc[mt][nt][3];
                *(float2*)&C[(size_t)row * N + col] = v0;
                *(float2*)&C[(size_t)(row + 8) * N + col] = v1;
            }
        }
    }
}

// ---------------------------------------------------------------------------
// Tensor-core sliding-window attention (bf16x3), pre-split inputs,
// cp.async staging, fused output split.
// ---------------------------------------------------------------------------
#define AT_KH 0
#define AT_KL 24576
#define AT_VH 49152
#define AT_VL 73728
#define AT_PN 98304
#define AT_RM 99072
#define AT_RS 99584
#define ATTN_SMEM 100096

__global__ __launch_bounds__(256, 2) void attn_mma_kernel(
    const __nv_bfloat16* __restrict__ qkvh, const __nv_bfloat16* __restrict__ qkvl,
    const float* __restrict__ pmask,
    __nv_bfloat16* __restrict__ ohi, __nv_bfloat16* __restrict__ olo)
{
    extern __shared__ __align__(128) char smem[];
    const uint32_t sb = smem_u32(smem);
    float* PNf = (float*)(smem + AT_PN);
    float* RMf = (float*)(smem + AT_RM);
    float* RSf = (float*)(smem + AT_RS);

    const int qt = blockIdx.x, h = blockIdx.y, b = blockIdx.z;
    const int q0 = qt * 64;
    const int kstart = q0 - 64;
    const int tid = threadIdx.x;
    const int wid = tid >> 5, lane = tid & 31;
    const int g = lane >> 2, tg = lane & 3;

    // ---- stage K/V hi/lo tiles via cp.async (zero-fill OOB keys) ----
    for (int idx = tid; idx < 192 * 8; idx += 256) {
        const int key = idx >> 3, u = idx & 7;
        const int gk = kstart + key;
        const uint32_t ok = (gk >= 0 && gk < SS) ? 16u : 0u;
        const int gkc = gk < 0 ? 0 : (gk >= SS ? SS - 1 : gk);
        const size_t base = ((size_t)(b * SS + gkc)) * (3 * DD) + h * HDIM + u * 8;
        const uint32_t swo = (uint32_t)(key * 128 + ((u * 16) ^ ((key & 7) << 4)));
        cp_async16z(sb + AT_KH + swo, qkvh + base + DD, ok);
        cp_async16z(sb + AT_KL + swo, qkvl + base + DD, ok);
        cp_async16z(sb + AT_VH + swo, qkvh + base + 2 * DD, ok);
        cp_async16z(sb + AT_VL + swo, qkvl + base + 2 * DD, ok);
    }
    CP_COMMIT();

    // ---- Q fragments: direct uint32 loads of pre-split hi/lo ----
    const int wm1 = wid >> 1, wn1 = wid & 1;
    uint32_t qh[4][4], ql[4][4];
    {
        const size_t qoff = ((size_t)(b * SS + q0 + wm1 * 16 + g)) * (3 * DD) + h * HDIM;
        const __nv_bfloat16* ph = qkvh + qoff;
        const __nv_bfloat16* pl = qkvl + qoff;
        const size_t r8 = (size_t)8 * (3 * DD);
        #pragma unroll
        for (int ks = 0; ks < 4; ks++) {
            const int c0 = ks * 16 + tg * 2;
            qh[ks][0] = *(const uint32_t*)(ph + c0);
            qh[ks][1] = *(const uint32_t*)(ph + r8 + c0);
            qh[ks][2] = *(const uint32_t*)(ph + c0 + 8);
            qh[ks][3] = *(const uint32_t*)(ph + r8 + c0 + 8);
            ql[ks][0] = *(const uint32_t*)(pl + c0);
            ql[ks][1] = *(const uint32_t*)(pl + r8 + c0);
            ql[ks][2] = *(const uint32_t*)(pl + c0 + 8);
            ql[ks][3] = *(const uint32_t*)(pl + r8 + c0 + 8);
        }
    }

    for (int j = tid; j < 192; j += 256) {
        const int gk = kstart + j;
        PNf[j] = (gk >= 0 && gk < SS) ? (1.0f - pmask[b * SS + gk]) * NEGV : -1e30f;
    }
    CP_WAIT0();
    __syncthreads();

    // ---- phase 1: S = Q K^T (bf16x3) ----
    float acc[12][4];
    #pragma unroll
    for (int nt = 0; nt < 12; nt++)
        #pragma unroll
        for (int c = 0; c < 4; c++) acc[nt][c] = 0.f;

    #pragma unroll
    for (int ks = 0; ks < 4; ks++) {
        #pragma unroll
        for (int nt = 0; nt < 12; nt++) {
            const int brow = wn1 * 96 + nt * 8 + (lane & 7);
            const uint32_t bo = (uint32_t)(brow * 128 +
                ((ks * 32 + ((lane >> 3) & 1) * 16) ^ ((lane & 7) << 4)));
            uint32_t bh[2], bl[2];
            LDSM_X2(bh[0], bh[1], sb + AT_KH + bo);
            LDSM_X2(bl[0], bl[1], sb + AT_KL + bo);
            mma16816(acc[nt], qh[ks], bh);
            mma16816(acc[nt], qh[ks], bl);
            mma16816(acc[nt], ql[ks], bh);
        }
    }

    // ---- mask + scale ----
    const int r0 = wm1 * 16 + g;
    const int r1 = r0 + 8;
    #pragma unroll
    for (int nt = 0; nt < 12; nt++) {
        const int j0 = wn1 * 96 + nt * 8 + tg * 2;
        #pragma unroll
        for (int e = 0; e < 4; e++) {
            const int j = j0 + (e & 1);
            const int rr = (e < 2) ? r0 : r1;
            const int diff = j - rr;
            acc[nt][e] = (diff >= 0 && diff <= 128)
                       ? acc[nt][e] * 0.125f + PNf[j] : -1e30f;
        }
    }

    // ---- softmax ----
    float m0 = -1e30f, m1 = -1e30f;
    #pragma unroll
    for (int nt = 0; nt < 12; nt++) {
        m0 = fmaxf(m0, fmaxf(acc[nt][0], acc[nt][1]));
        m1 = fmaxf(m1, fmaxf(acc[nt][2], acc[nt][3]));
    }
    #pragma unroll
    for (int o = 1; o <= 2; o <<= 1) {
        m0 = fmaxf(m0, __shfl_xor_sync(0xffffffffu, m0, o));
        m1 = fmaxf(m1, __shfl_xor_sync(0xffffffffu, m1, o));
    }
    if (tg == 0) { RMf[r0 * 2 + wn1] = m0; RMf[r1 * 2 + wn1] = m1; }
    __syncthreads();
    m0 = fmaxf(RMf[r0 * 2], RMf[r0 * 2 + 1]);
    m1 = fmaxf(RMf[r1 * 2], RMf[r1 * 2 + 1]);

    float s0 = 0.f, s1 = 0.f;
    #pragma unroll
    for (int nt = 0; nt < 12; nt++) {
        acc[nt][0] = __expf(acc[nt][0] - m0);
        acc[nt][1] = __expf(acc[nt][1] - m0);
        acc[nt][2] = __expf(acc[nt][2] - m1);
        acc[nt][3] = __expf(acc[nt][3] - m1);
        s0 += acc[nt][0] + acc[nt][1];
        s1 += acc[nt][2] + acc[nt][3];
    }
    #pragma unroll
    for (int o = 1; o <= 2; o <<= 1) {
        s0 += __shfl_xor_sync(0xffffffffu, s0, o);
        s1 += __shfl_xor_sync(0xffffffffu, s1, o);
    }
    if (tg == 0) { RSf[r0 * 2 + wn1] = s0; RSf[r1 * 2 + wn1] = s1; }
    __syncthreads();
    const float inv0 = 1.f / (RSf[r0 * 2] + RSf[r0 * 2 + 1]);
    const float inv1 = 1.f / (RSf[r1 * 2] + RSf[r1 * 2 + 1]);

    // ---- write P hi/lo over dead K region ----
    #pragma unroll
    for (int nt = 0; nt < 12; nt++) {
        const int j0 = wn1 * 96 + nt * 8 + tg * 2;
        uint32_t hi, lo;
        split2(acc[nt][0] * inv0, acc[nt][1] * inv0, hi, lo);
        uint32_t o0 = (uint32_t)(r0 * 384 + ((j0 * 2) ^ ((r0 & 7) << 4)));
        *(uint32_t*)(smem + AT_KH + o0) = hi;
        *(uint32_t*)(smem + AT_KL + o0) = lo;
        split2(acc[nt][2] * inv1, acc[nt][3] * inv1, hi, lo);
        uint32_t o1 = (uint32_t)(r1 * 384 + ((j0 * 2) ^ ((r1 & 7) << 4)));
        *(uint32_t*)(smem + AT_KH + o1) = hi;
        *(uint32_t*)(smem + AT_KL + o1) = lo;
    }
    __syncthreads();

    // ---- phase 2: O = P V ----
    const int wm3 = wm1, wn3 = wn1;
    float oacc[4][4];
    #pragma unroll
    for (int nt = 0; nt < 4; nt++)
        #pragma unroll
        for (int c = 0; c < 4; c++) oacc[nt][c] = 0.f;

    #pragma unroll
    for (int ks = 0; ks < 12; ks++) {
        const int prow = wm3 * 16 + (lane & 15);
        const uint32_t po = (uint32_t)(prow * 384 +
            ((ks * 32 + (lane >> 4) * 16) ^ ((prow & 7) << 4)));
        uint32_t ph[4], pl[4];
        LDSM_X4(ph[0], ph[1], ph[2], ph[3], sb + AT_KH + po);
        LDSM_X4(pl[0], pl[1], pl[2], pl[3], sb + AT_KL + po);
        #pragma unroll
        for (int nt = 0; nt < 4; nt++) {
            const int vrow = ks * 16 + (lane & 15);
            const uint32_t vo = (uint32_t)(vrow * 128 +
                (((wn3 * 32 + nt * 8) * 2) ^ ((vrow & 7) << 4)));
            uint32_t vh[2], vl[2];
            LDSM_X2T(vh[0], vh[1], sb + AT_VH + vo);
            LDSM_X2T(vl[0], vl[1], sb + AT_VL + vo);
            mma16816(oacc[nt], ph, vh);
            mma16816(oacc[nt], ph, vl);
            mma16816(oacc[nt], pl, vh);
        }
    }

    // ---- epilogue: fused output split ----
    #pragma unroll
    for (int nt = 0; nt < 4; nt++) {
        const int gq0 = q0 + wm3 * 16 + g;
        const int col = h * HDIM + wn3 * 32 + nt * 8 + tg * 2;
        uint32_t hi, lo;
        size_t off = ((size_t)(b * SS + gq0)) * DD + col;
        split2(oacc[nt][0], oacc[nt][1], hi, lo);
        *(uint32_t*)(ohi + off) = hi;
        *(uint32_t*)(olo + off) = lo;
        off += (size_t)8 * DD;
        split2(oacc[nt][2], oacc[nt][3], hi, lo);
        *(uint32_t*)(ohi + off) = hi;
        *(uint32_t*)(olo + off) = lo;
    }
}

// ---------------------------------------------------------------------------
extern "C" void kernel_launch(void* const* d_in, const int* in_sizes, int n_in,
                              void* d_out, int out_size)
{
    const float* x    = (const float*)d_in[0];
    const float* pm   = (const float*)d_in[1];
    const float* Wqkv = (const float*)d_in[2];
    const float* Wo   = (const float*)d_in[3];
    float* out = (float*)d_out;

    __nv_bfloat16 *qkvh, *qkvl, *xhi, *xlo, *wqh, *wql, *woh, *wol, *ahi, *alo;
    cudaGetSymbolAddress((void**)&qkvh, g_qkvh);
    cudaGetSymbolAddress((void**)&qkvl, g_qkvl);
    cudaGetSymbolAddress((void**)&xhi, g_xhi);
    cudaGetSymbolAddress((void**)&xlo, g_xlo);
    cudaGetSymbolAddress((void**)&wqh, g_wqh);
    cudaGetSymbolAddress((void**)&wql, g_wql);
    cudaGetSymbolAddress((void**)&woh, g_woh);
    cudaGetSymbolAddress((void**)&wol, g_wol);
    cudaGetSymbolAddress((void**)&ahi, g_ahi);
    cudaGetSymbolAddress((void**)&alo, g_alo);

    const int M = BB * SS;            // 4096
    const int nx = M * DD;            // 3.1M

    static bool attr_done = false;
    if (!attr_done) {
        cudaFuncSetAttribute(gemm_bf16x3_kernel<true>,
                             cudaFuncAttributeMaxDynamicSharedMemorySize, GEMM_SMEM);
        cudaFuncSetAttribute(gemm_bf16x3_kernel<false>,
                             cudaFuncAttributeMaxDynamicSharedMemorySize, GEMM_SMEM);
        cudaFuncSetAttribute(attn_mma_kernel,
                             cudaFuncAttributeMaxDynamicSharedMemorySize, ATTN_SMEM);
        attr_done = true;
    }

    // Input conversions
    split_kernel<<<(nx + 255) / 256, 256>>>(x, xhi, xlo, nx);
    splitT_kernel<<<dim3(3 * DD / 32, DD / 32), dim3(32, 8)>>>(Wqkv, wqh, wql, DD, 3 * DD);
    splitT_kernel<<<dim3(DD / 32, DD / 32), dim3(32, 8)>>>(Wo, woh, wol, DD, DD);

    // 1) QKV projection (tensor cores), writes bf16 hi/lo split directly
    gemm_bf16x3_kernel<true><<<dim3(3 * DD / 128, M / 128), 256, GEMM_SMEM>>>(
        xhi, xlo, wqh, wql, nullptr, qkvh, qkvl, M, 3 * DD, DD);

    // 2) Sliding-window attention (tensor cores), pre-split I/O
    attn_mma_kernel<<<dim3(SS / 64, HH, BB), 256, ATTN_SMEM>>>(qkvh, qkvl, pm, ahi, alo);

    // 3) Output projection (tensor cores), fp32 out
    gemm_bf16x3_kernel<false><<<dim3(DD / 128, M / 128), 256, GEMM_SMEM>>>(
        ahi, alo, woh, wol, out, nullptr, nullptr, M, DD, DD);
}

// round 13
// speedup vs baseline: 1.5435x; 1.5435x over previous
#include <cuda_runtime.h>
#include <cuda_bf16.h>
#include <cstdint>
#include <math.h>

// Problem constants
#define BB   2
#define SS   2048
#define DD   768
#define HH   12
#define HDIM 64
#define HALFW 64
#define NEGV -1000000000.0f

// ---------------------------------------------------------------------------
// Scratch (no cudaMalloc allowed)
// ---------------------------------------------------------------------------
__device__ float g_qkv[BB * SS * 3 * DD];            // fp32 qkv  (4096 x 2304)
__device__ __nv_bfloat16 g_xhi[BB * SS * DD];        // x split
__device__ __nv_bfloat16 g_xlo[BB * SS * DD];
__device__ __nv_bfloat16 g_wqh[3 * DD * DD];         // Wqkv^T split (2304 x 768)
__device__ __nv_bfloat16 g_wql[3 * DD * DD];
__device__ __nv_bfloat16 g_woh[DD * DD];             // Wo^T split (768 x 768)
__device__ __nv_bfloat16 g_wol[DD * DD];
__device__ __nv_bfloat16 g_ahi[BB * SS * DD];        // attn out split (written by attn)
__device__ __nv_bfloat16 g_alo[BB * SS * DD];

// ---------------------------------------------------------------------------
// Common helpers
// ---------------------------------------------------------------------------
__device__ __forceinline__ uint32_t smem_u32(const void* p) {
    uint32_t a;
    asm("{ .reg .u64 t; cvta.to.shared.u64 t, %1; cvt.u32.u64 %0, t; }"
        : "=r"(a) : "l"(p));
    return a;
}

__device__ __forceinline__ void cp_async16(uint32_t dst, const void* src) {
    asm volatile("cp.async.cg.shared.global [%0], [%1], 16;" :: "r"(dst), "l"(src));
}
#define CP_COMMIT() asm volatile("cp.async.commit_group;" ::: "memory")
#define CP_WAIT1()  asm volatile("cp.async.wait_group 1;" ::: "memory")

#define LDSM_X4(r0, r1, r2, r3, addr) \
    asm volatile("ldmatrix.sync.aligned.m8n8.x4.shared.b16 {%0,%1,%2,%3}, [%4];" \
                 : "=r"(r0), "=r"(r1), "=r"(r2), "=r"(r3) : "r"(addr))
#define LDSM_X2(r0, r1, addr) \
    asm volatile("ldmatrix.sync.aligned.m8n8.x2.shared.b16 {%0,%1}, [%2];" \
                 : "=r"(r0), "=r"(r1) : "r"(addr))
#define LDSM_X2T(r0, r1, addr) \
    asm volatile("ldmatrix.sync.aligned.m8n8.x2.trans.shared.b16 {%0,%1}, [%2];" \
                 : "=r"(r0), "=r"(r1) : "r"(addr))

__device__ __forceinline__ void mma16816(float* c, const uint32_t* a, const uint32_t* b)
{
    asm volatile(
        "mma.sync.aligned.m16n8k16.row.col.f32.bf16.bf16.f32 "
        "{%0,%1,%2,%3}, {%4,%5,%6,%7}, {%8,%9}, {%0,%1,%2,%3};"
        : "+f"(c[0]), "+f"(c[1]), "+f"(c[2]), "+f"(c[3])
        : "r"(a[0]), "r"(a[1]), "r"(a[2]), "r"(a[3]), "r"(b[0]), "r"(b[1]));
}

__device__ __forceinline__ void split2(float a, float b, uint32_t& hi, uint32_t& lo)
{
    __nv_bfloat16 ha = __float2bfloat16(a), hb = __float2bfloat16(b);
    __nv_bfloat16 la = __float2bfloat16(a - __bfloat162float(ha));
    __nv_bfloat16 lb = __float2bfloat16(b - __bfloat162float(hb));
    hi = ((uint32_t)__bfloat16_as_ushort(hb) << 16) | (uint32_t)__bfloat16_as_ushort(ha);
    lo = ((uint32_t)__bfloat16_as_ushort(lb) << 16) | (uint32_t)__bfloat16_as_ushort(la);
}

// ---------------------------------------------------------------------------
// Merged conversion kernel: one launch does all three independent jobs.
//   blocks [0, NB_X)                 : vectorized split of x (float4 -> uint2 pair)
//   blocks [NB_X, NB_X+NB_WQ)        : transpose-split of Wqkv (32x32 tiles)
//   blocks [NB_X+NB_WQ, +NB_WO)      : transpose-split of Wo
// ---------------------------------------------------------------------------
#define NB_X  3072      // 4096*768 / 4 / 256
#define NB_WQ 1728      // (2304/32) * (768/32) = 72 * 24
#define NB_WO 576       // 24 * 24
#define NB_ALL (NB_X + NB_WQ + NB_WO)

__device__ __forceinline__ void splitT_tile(
    const float* __restrict__ in, __nv_bfloat16* __restrict__ hiT,
    __nv_bfloat16* __restrict__ loT, int K, int N, int k0, int n0,
    int tid, float (*t)[33])
{
    const int tx = tid & 31, ty = tid >> 5;     // 32 x 8
    #pragma unroll
    for (int i = 0; i < 32; i += 8)
        t[ty + i][tx] = in[(size_t)(k0 + ty + i) * N + n0 + tx];
    __syncthreads();
    #pragma unroll
    for (int i = 0; i < 32; i += 8) {
        float v = t[tx][ty + i];
        __nv_bfloat16 h = __float2bfloat16(v);
        size_t o = (size_t)(n0 + ty + i) * K + k0 + tx;
        hiT[o] = h;
        loT[o] = __float2bfloat16(v - __bfloat162float(h));
    }
}

__global__ __launch_bounds__(256) void conv_all_kernel(
    const float* __restrict__ x, const float* __restrict__ Wqkv,
    const float* __restrict__ Wo,
    __nv_bfloat16* __restrict__ xhi, __nv_bfloat16* __restrict__ xlo,
    __nv_bfloat16* __restrict__ wqh, __nv_bfloat16* __restrict__ wql,
    __nv_bfloat16* __restrict__ woh, __nv_bfloat16* __restrict__ wol)
{
    __shared__ float t[32][33];
    const int bid = blockIdx.x, tid = threadIdx.x;

    if (bid < NB_X) {
        // x split, 4 elems/thread
        const int gid = bid * 256 + tid;
        float4 v = ((const float4*)x)[gid];
        uint2 hi, lo;
        split2(v.x, v.y, hi.x, lo.x);
        split2(v.z, v.w, hi.y, lo.y);
        ((uint2*)xhi)[gid] = hi;
        ((uint2*)xlo)[gid] = lo;
    } else if (bid < NB_X + NB_WQ) {
        const int b2 = bid - NB_X;
        const int n0 = (b2 % 72) * 32, k0 = (b2 / 72) * 32;
        splitT_tile(Wqkv, wqh, wql, DD, 3 * DD, k0, n0, tid, t);
    } else {
        const int b3 = bid - NB_X - NB_WQ;
        const int n0 = (b3 % 24) * 32, k0 = (b3 / 24) * 32;
        splitT_tile(Wo, woh, wol, DD, DD, k0, n0, tid, t);
    }
}

// ---------------------------------------------------------------------------
// bf16x3 mma.sync GEMM (round-7 proven shape: BK=32, 2-stage cp.async,
// ldmatrix, fp32 epilogue). C[M,N] = A[M,K] @ Bt[N,K]^T.
// ---------------------------------------------------------------------------
#define SMS 40
#define TILE_BYTES (128 * SMS * 2)
#define STAGE_BYTES (4 * TILE_BYTES)
#define GEMM_SMEM (2 * STAGE_BYTES)

__global__ __launch_bounds__(256) void gemm_bf16x3_kernel(
    const __nv_bfloat16* __restrict__ Ahi, const __nv_bfloat16* __restrict__ Alo,
    const __nv_bfloat16* __restrict__ Bthi, const __nv_bfloat16* __restrict__ Btlo,
    float* __restrict__ C, int M, int N, int K)
{
    extern __shared__ __align__(128) char smem[];
    const uint32_t smem_base = smem_u32(smem);

    const int tid = threadIdx.x;
    const int wid = tid >> 5, lane = tid & 31;
    const int g = lane >> 2, tg = lane & 3;
    const int wm = wid >> 2, wn = wid & 3;
    const int mbase = wm * 64, nbase = wn * 32;
    const int bm = blockIdx.y * 128, bn = blockIdx.x * 128;

    const __nv_bfloat16* srcs[4] = {
        Ahi + (size_t)bm * K, Alo + (size_t)bm * K,
        Bthi + (size_t)bn * K, Btlo + (size_t)bn * K };

    const int niter = K >> 5;
    const int lr0 = tid >> 2, lq = tid & 3;
    const uint32_t st_off = (uint32_t)(lr0 * SMS + lq * 8) * 2;

    const uint32_t a_lane = (uint32_t)((lane & 15) * (SMS * 2) + ((lane >> 4) << 4));
    const uint32_t b_lane = (uint32_t)((lane & 7) * (SMS * 2) + (((lane >> 3) & 1) << 4));

    float acc[4][4][4];
    #pragma unroll
    for (int i = 0; i < 4; i++)
        #pragma unroll
        for (int j = 0; j < 4; j++)
            #pragma unroll
            for (int c = 0; c < 4; c++) acc[i][j][c] = 0.f;

    #pragma unroll
    for (int p = 0; p < 2; p++) {
        if (p < niter) {
            const int k0 = p << 5;
            const uint32_t sb = smem_base + (uint32_t)p * STAGE_BYTES;
            #pragma unroll
            for (int t = 0; t < 4; t++) {
                const __nv_bfloat16* s = srcs[t] + k0 + lq * 8;
                uint32_t d = sb + (uint32_t)t * TILE_BYTES + st_off;
                cp_async16(d, s + (size_t)lr0 * K);
                cp_async16(d + 64 * SMS * 2, s + (size_t)(lr0 + 64) * K);
            }
        }
        CP_COMMIT();
    }

    for (int it = 0; it < niter; it++) {
        CP_WAIT1();
        __syncthreads();

        const uint32_t sb = smem_base + (uint32_t)(it & 1) * STAGE_BYTES;
        const uint32_t aAh = sb + a_lane;
        const uint32_t aAl = sb + TILE_BYTES + a_lane;
        const uint32_t aBh = sb + 2 * TILE_BYTES + b_lane;
        const uint32_t aBl = sb + 3 * TILE_BYTES + b_lane;

        #pragma unroll
        for (int kk = 0; kk < 32; kk += 16) {
            uint32_t ah[4][4], al[4][4], bh[4][2], bl[4][2];
            #pragma unroll
            for (int mt = 0; mt < 4; mt++) {
                const uint32_t ro = (uint32_t)((mbase + mt * 16) * (SMS * 2) + kk * 2);
                LDSM_X4(ah[mt][0], ah[mt][1], ah[mt][2], ah[mt][3], aAh + ro);
                LDSM_X4(al[mt][0], al[mt][1], al[mt][2], al[mt][3], aAl + ro);
            }
            #pragma unroll
            for (int nt = 0; nt < 4; nt++) {
                const uint32_t ro = (uint32_t)((nbase + nt * 8) * (SMS * 2) + kk * 2);
                LDSM_X2(bh[nt][0], bh[nt][1], aBh + ro);
                LDSM_X2(bl[nt][0], bl[nt][1], aBl + ro);
            }
            #pragma unroll
            for (int mt = 0; mt < 4; mt++)
                #pragma unroll
                for (int nt = 0; nt < 4; nt++)
                    mma16816(acc[mt][nt], ah[mt], bh[nt]);
            #pragma unroll
            for (int mt = 0; mt < 4; mt++)
                #pragma unroll
                for (int nt = 0; nt < 4; nt++)
                    mma16816(acc[mt][nt], ah[mt], bl[nt]);
            #pragma unroll
            for (int mt = 0; mt < 4; mt++)
                #pragma unroll
                for (int nt = 0; nt < 4; nt++)
                    mma16816(acc[mt][nt], al[mt], bh[nt]);
        }
        __syncthreads();

        const int nx = it + 2;
        if (nx < niter) {
            const int k0 = nx << 5;
            const uint32_t db = smem_base + (uint32_t)(nx & 1) * STAGE_BYTES;
            #pragma unroll
            for (int t = 0; t < 4; t++) {
                const __nv_bfloat16* s = srcs[t] + k0 + lq * 8;
                uint32_t d = db + (uint32_t)t * TILE_BYTES + st_off;
                cp_async16(d, s + (size_t)lr0 * K);
                cp_async16(d + 64 * SMS * 2, s + (size_t)(lr0 + 64) * K);
            }
        }
        CP_COMMIT();
    }

    #pragma unroll
    for (int mt = 0; mt < 4; mt++) {
        #pragma unroll
        for (int nt = 0; nt < 4; nt++) {
            const int row = bm + mbase + mt * 16 + g;
            const int col = bn + nbase + nt * 8 + tg * 2;
            float2 v0; v0.x = acc[mt][nt][0]; v0.y = acc[mt][nt][1];
            float2 v1; v1.x = acc[mt][nt][2]; v1.y = acc[mt][nt][3];
            *(float2*)&C[(size_t)row * N + col] = v0;
            *(float2*)&C[(size_t)(row + 8) * N + col] = v1;
        }
    }
}

// ---------------------------------------------------------------------------
// Tensor-core sliding-window attention (bf16x3), fused output split.
// (exact round-7 version)
// ---------------------------------------------------------------------------
#define AT_KH 0
#define AT_KL 24576
#define AT_VH 49152
#define AT_VL 73728
#define AT_PN 98304
#define AT_RM 99072
#define AT_RS 99584
#define ATTN_SMEM 100096

__global__ __launch_bounds__(256, 2) void attn_mma_kernel(
    const float* __restrict__ qkv, const float* __restrict__ pmask,
    __nv_bfloat16* __restrict__ ohi, __nv_bfloat16* __restrict__ olo)
{
    extern __shared__ __align__(128) char smem[];
    const uint32_t sb = smem_u32(smem);
    float* PNf = (float*)(smem + AT_PN);
    float* RMf = (float*)(smem + AT_RM);
    float* RSf = (float*)(smem + AT_RS);

    const int qt = blockIdx.x, h = blockIdx.y, b = blockIdx.z;
    const int q0 = qt * 64;
    const int kstart = q0 - 64;
    const int tid = threadIdx.x;
    const int wid = tid >> 5, lane = tid & 31;
    const int g = lane >> 2, tg = lane & 3;

    const int wm1 = wid >> 1, wn1 = wid & 1;
    uint32_t qh[4][4], ql[4][4];
    {
        const float* qr0 = qkv + ((size_t)(b * SS + q0 + wm1 * 16 + g)) * (3 * DD) + h * HDIM;
        const float* qr8 = qr0 + (size_t)8 * (3 * DD);
        #pragma unroll
        for (int ks = 0; ks < 4; ks++) {
            float2 x0 = *(const float2*)(qr0 + ks * 16 + tg * 2);
            float2 x1 = *(const float2*)(qr8 + ks * 16 + tg * 2);
            float2 x2 = *(const float2*)(qr0 + ks * 16 + 8 + tg * 2);
            float2 x3 = *(const float2*)(qr8 + ks * 16 + 8 + tg * 2);
            split2(x0.x, x0.y, qh[ks][0], ql[ks][0]);
            split2(x1.x, x1.y, qh[ks][1], ql[ks][1]);
            split2(x2.x, x2.y, qh[ks][2], ql[ks][2]);
            split2(x3.x, x3.y, qh[ks][3], ql[ks][3]);
        }
    }

    for (int idx = tid; idx < 192 * 8; idx += 256) {
        const int key = idx >> 3, u = idx & 7;
        const int gk = kstart + key;
        float4 kv0, kv1, vv0, vv1;
        if (gk >= 0 && gk < SS) {
            const float* base = qkv + ((size_t)(b * SS + gk)) * (3 * DD) + h * HDIM + u * 8;
            kv0 = *(const float4*)(base + DD);
            kv1 = *(const float4*)(base + DD + 4);
            vv0 = *(const float4*)(base + 2 * DD);
            vv1 = *(const float4*)(base + 2 * DD + 4);
        } else {
            kv0 = kv1 = vv0 = vv1 = make_float4(0.f, 0.f, 0.f, 0.f);
        }
        const uint32_t swo = (uint32_t)(key * 128 + ((u * 16) ^ ((key & 7) << 4)));
        uint4 hi4, lo4;
        split2(kv0.x, kv0.y, hi4.x, lo4.x);
        split2(kv0.z, kv0.w, hi4.y, lo4.y);
        split2(kv1.x, kv1.y, hi4.z, lo4.z);
        split2(kv1.z, kv1.w, hi4.w, lo4.w);
        *(uint4*)(smem + AT_KH + swo) = hi4;
        *(uint4*)(smem + AT_KL + swo) = lo4;
        split2(vv0.x, vv0.y, hi4.x, lo4.x);
        split2(vv0.z, vv0.w, hi4.y, lo4.y);
        split2(vv1.x, vv1.y, hi4.z, lo4.z);
        split2(vv1.z, vv1.w, hi4.w, lo4.w);
        *(uint4*)(smem + AT_VH + swo) = hi4;
        *(uint4*)(smem + AT_VL + swo) = lo4;
    }
    for (int j = tid; j < 192; j += 256) {
        const int gk = kstart + j;
        PNf[j] = (gk >= 0 && gk < SS) ? (1.0f - pmask[b * SS + gk]) * NEGV : -1e30f;
    }
    __syncthreads();

    float acc[12][4];
    #pragma unroll
    for (int nt = 0; nt < 12; nt++)
        #pragma unroll
        for (int c = 0; c < 4; c++) acc[nt][c] = 0.f;

    #pragma unroll
    for (int ks = 0; ks < 4; ks++) {
        #pragma unroll
        for (int nt = 0; nt < 12; nt++) {
            const int brow = wn1 * 96 + nt * 8 + (lane & 7);
            const uint32_t bo = (uint32_t)(brow * 128 +
                ((ks * 32 + ((lane >> 3) & 1) * 16) ^ ((lane & 7) << 4)));
            uint32_t bh[2], bl[2];
            LDSM_X2(bh[0], bh[1], sb + AT_KH + bo);
            LDSM_X2(bl[0], bl[1], sb + AT_KL + bo);
            mma16816(acc[nt], qh[ks], bh);
            mma16816(acc[nt], qh[ks], bl);
            mma16816(acc[nt], ql[ks], bh);
        }
    }

    const int r0 = wm1 * 16 + g;
    const int r1 = r0 + 8;
    #pragma unroll
    for (int nt = 0; nt < 12; nt++) {
        const int j0 = wn1 * 96 + nt * 8 + tg * 2;
        #pragma unroll
        for (int e = 0; e < 4; e++) {
            const int j = j0 + (e & 1);
            const int rr = (e < 2) ? r0 : r1;
            const int diff = j - rr;
            acc[nt][e] = (diff >= 0 && diff <= 128)
                       ? acc[nt][e] * 0.125f + PNf[j] : -1e30f;
        }
    }

    float m0 = -1e30f, m1 = -1e30f;
    #pragma unroll
    for (int nt = 0; nt < 12; nt++) {
        m0 = fmaxf(m0, fmaxf(acc[nt][0], acc[nt][1]));
        m1 = fmaxf(m1, fmaxf(acc[nt][2], acc[nt][3]));
    }
    #pragma unroll
    for (int o = 1; o <= 2; o <<= 1) {
        m0 = fmaxf(m0, __shfl_xor_sync(0xffffffffu, m0, o));
        m1 = fmaxf(m1, __shfl_xor_sync(0xffffffffu, m1, o));
    }
    if (tg == 0) { RMf[r0 * 2 + wn1] = m0; RMf[r1 * 2 + wn1] = m1; }
    __syncthreads();
    m0 = fmaxf(RMf[r0 * 2], RMf[r0 * 2 + 1]);
    m1 = fmaxf(RMf[r1 * 2], RMf[r1 * 2 + 1]);

    float s0 = 0.f, s1 = 0.f;
    #pragma unroll
    for (int nt = 0; nt < 12; nt++) {
        acc[nt][0] = __expf(acc[nt][0] - m0);
        acc[nt][1] = __expf(acc[nt][1] - m0);
        acc[nt][2] = __expf(acc[nt][2] - m1);
        acc[nt][3] = __expf(acc[nt][3] - m1);
        s0 += acc[nt][0] + acc[nt][1];
        s1 += acc[nt][2] + acc[nt][3];
    }
    #pragma unroll
    for (int o = 1; o <= 2; o <<= 1) {
        s0 += __shfl_xor_sync(0xffffffffu, s0, o);
        s1 += __shfl_xor_sync(0xffffffffu, s1, o);
    }
    if (tg == 0) { RSf[r0 * 2 + wn1] = s0; RSf[r1 * 2 + wn1] = s1; }
    __syncthreads();
    const float inv0 = 1.f / (RSf[r0 * 2] + RSf[r0 * 2 + 1]);
    const float inv1 = 1.f / (RSf[r1 * 2] + RSf[r1 * 2 + 1]);

    #pragma unroll
    for (int nt = 0; nt < 12; nt++) {
        const int j0 = wn1 * 96 + nt * 8 + tg * 2;
        uint32_t hi, lo;
        split2(acc[nt][0] * inv0, acc[nt][1] * inv0, hi, lo);
        uint32_t o0 = (uint32_t)(r0 * 384 + ((j0 * 2) ^ ((r0 & 7) << 4)));
        *(uint32_t*)(smem + AT_KH + o0) = hi;
        *(uint32_t*)(smem + AT_KL + o0) = lo;
        split2(acc[nt][2] * inv1, acc[nt][3] * inv1, hi, lo);
        uint32_t o1 = (uint32_t)(r1 * 384 + ((j0 * 2) ^ ((r1 & 7) << 4)));
        *(uint32_t*)(smem + AT_KH + o1) = hi;
        *(uint32_t*)(smem + AT_KL + o1) = lo;
    }
    __syncthreads();

    const int wm3 = wm1, wn3 = wn1;
    float oacc[4][4];
    #pragma unroll
    for (int nt = 0; nt < 4; nt++)
        #pragma unroll
        for (int c = 0; c < 4; c++) oacc[nt][c] = 0.f;

    #pragma unroll
    for (int ks = 0; ks < 12; ks++) {
        const int prow = wm3 * 16 + (lane & 15);
        const uint32_t po = (uint32_t)(prow * 384 +
            ((ks * 32 + (lane >> 4) * 16) ^ ((prow & 7) << 4)));
        uint32_t ph[4], pl[4];
        LDSM_X4(ph[0], ph[1], ph[2], ph[3], sb + AT_KH + po);
        LDSM_X4(pl[0], pl[1], pl[2], pl[3], sb + AT_KL + po);
        #pragma unroll
        for (int nt = 0; nt < 4; nt++) {
            const int vrow = ks * 16 + (lane & 15);
            const uint32_t vo = (uint32_t)(vrow * 128 +
                (((wn3 * 32 + nt * 8) * 2) ^ ((vrow & 7) << 4)));
            uint32_t vh[2], vl[2];
            LDSM_X2T(vh[0], vh[1], sb + AT_VH + vo);
            LDSM_X2T(vl[0], vl[1], sb + AT_VL + vo);
            mma16816(oacc[nt], ph, vh);
            mma16816(oacc[nt], ph, vl);
            mma16816(oacc[nt], pl, vh);
        }
    }

    #pragma unroll
    for (int nt = 0; nt < 4; nt++) {
        const int gq0 = q0 + wm3 * 16 + g;
        const int col = h * HDIM + wn3 * 32 + nt * 8 + tg * 2;
        uint32_t hi, lo;
        size_t off = ((size_t)(b * SS + gq0)) * DD + col;
        split2(oacc[nt][0], oacc[nt][1], hi, lo);
        *(uint32_t*)(ohi + off) = hi;
        *(uint32_t*)(olo + off) = lo;
        off += (size_t)8 * DD;
        split2(oacc[nt][2], oacc[nt][3], hi, lo);
        *(uint32_t*)(ohi + off) = hi;
        *(uint32_t*)(olo + off) = lo;
    }
}

// ---------------------------------------------------------------------------
extern "C" void kernel_launch(void* const* d_in, const int* in_sizes, int n_in,
                              void* d_out, int out_size)
{
    const float* x    = (const float*)d_in[0];
    const float* pm   = (const float*)d_in[1];
    const float* Wqkv = (const float*)d_in[2];
    const float* Wo   = (const float*)d_in[3];
    float* out = (float*)d_out;

    float* qkv_p;
    __nv_bfloat16 *xhi, *xlo, *wqh, *wql, *woh, *wol, *ahi, *alo;
    cudaGetSymbolAddress((void**)&qkv_p, g_qkv);
    cudaGetSymbolAddress((void**)&xhi, g_xhi);
    cudaGetSymbolAddress((void**)&xlo, g_xlo);
    cudaGetSymbolAddress((void**)&wqh, g_wqh);
    cudaGetSymbolAddress((void**)&wql, g_wql);
    cudaGetSymbolAddress((void**)&woh, g_woh);
    cudaGetSymbolAddress((void**)&wol, g_wol);
    cudaGetSymbolAddress((void**)&ahi, g_ahi);
    cudaGetSymbolAddress((void**)&alo, g_alo);

    const int M = BB * SS;            // 4096

    static bool attr_done = false;
    if (!attr_done) {
        cudaFuncSetAttribute(gemm_bf16x3_kernel,
                             cudaFuncAttributeMaxDynamicSharedMemorySize, GEMM_SMEM);
        cudaFuncSetAttribute(attn_mma_kernel,
                             cudaFuncAttributeMaxDynamicSharedMemorySize, ATTN_SMEM);
        attr_done = true;
    }

    // 0) All input conversions in one launch (x split + both weight T-splits)
    conv_all_kernel<<<NB_ALL, 256>>>(x, Wqkv, Wo, xhi, xlo, wqh, wql, woh, wol);

    // 1) QKV projection (tensor cores)
    gemm_bf16x3_kernel<<<dim3(3 * DD / 128, M / 128), 256, GEMM_SMEM>>>(
        xhi, xlo, wqh, wql, qkv_p, M, 3 * DD, DD);

    // 2) Sliding-window attention (tensor cores), writes bf16 hi/lo directly
    attn_mma_kernel<<<dim3(SS / 64, HH, BB), 256, ATTN_SMEM>>>(qkv_p, pm, ahi, alo);

    // 3) Output projection (tensor cores)
    gemm_bf16x3_kernel<<<dim3(DD / 128, M / 128), 256, GEMM_SMEM>>>(
        ahi, alo, woh, wol, out, M, DD, DD);
}

// round 17
// speedup vs baseline: 1.6849x; 1.0916x over previous
#include <cuda_runtime.h>
#include <cuda_bf16.h>
#include <cstdint>
#include <math.h>

// Problem constants
#define BB   2
#define SS   2048
#define DD   768
#define HH   12
#define HDIM 64
#define HALFW 64
#define NEGV -1000000000.0f

// ---------------------------------------------------------------------------
// Scratch (no cudaMalloc allowed)
// ---------------------------------------------------------------------------
__device__ float g_qkv[BB * SS * 3 * DD];            // fp32 qkv  (4096 x 2304)
__device__ __nv_bfloat16 g_xhi[BB * SS * DD];        // x split
__device__ __nv_bfloat16 g_xlo[BB * SS * DD];
__device__ __nv_bfloat16 g_wqh[3 * DD * DD];         // Wqkv^T split (2304 x 768)
__device__ __nv_bfloat16 g_wql[3 * DD * DD];
__device__ __nv_bfloat16 g_woh[DD * DD];             // Wo^T split (768 x 768)
__device__ __nv_bfloat16 g_wol[DD * DD];
__device__ __nv_bfloat16 g_ahi[BB * SS * DD];        // attn out split (written by attn)
__device__ __nv_bfloat16 g_alo[BB * SS * DD];

// ---------------------------------------------------------------------------
// Common helpers
// ---------------------------------------------------------------------------
__device__ __forceinline__ uint32_t smem_u32(const void* p) {
    uint32_t a;
    asm("{ .reg .u64 t; cvta.to.shared.u64 t, %1; cvt.u32.u64 %0, t; }"
        : "=r"(a) : "l"(p));
    return a;
}

__device__ __forceinline__ void cp_async16(uint32_t dst, const void* src) {
    asm volatile("cp.async.cg.shared.global [%0], [%1], 16;" :: "r"(dst), "l"(src));
}
#define CP_COMMIT() asm volatile("cp.async.commit_group;" ::: "memory")
#define CP_WAIT1()  asm volatile("cp.async.wait_group 1;" ::: "memory")

#define LDSM_X4(r0, r1, r2, r3, addr) \
    asm volatile("ldmatrix.sync.aligned.m8n8.x4.shared.b16 {%0,%1,%2,%3}, [%4];" \
                 : "=r"(r0), "=r"(r1), "=r"(r2), "=r"(r3) : "r"(addr))
#define LDSM_X2(r0, r1, addr) \
    asm volatile("ldmatrix.sync.aligned.m8n8.x2.shared.b16 {%0,%1}, [%2];" \
                 : "=r"(r0), "=r"(r1) : "r"(addr))
#define LDSM_X2T(r0, r1, addr) \
    asm volatile("ldmatrix.sync.aligned.m8n8.x2.trans.shared.b16 {%0,%1}, [%2];" \
                 : "=r"(r0), "=r"(r1) : "r"(addr))

__device__ __forceinline__ void mma16816(float* c, const uint32_t* a, const uint32_t* b)
{
    asm volatile(
        "mma.sync.aligned.m16n8k16.row.col.f32.bf16.bf16.f32 "
        "{%0,%1,%2,%3}, {%4,%5,%6,%7}, {%8,%9}, {%0,%1,%2,%3};"
        : "+f"(c[0]), "+f"(c[1]), "+f"(c[2]), "+f"(c[3])
        : "r"(a[0]), "r"(a[1]), "r"(a[2]), "r"(a[3]), "r"(b[0]), "r"(b[1]));
}

__device__ __forceinline__ void split2(float a, float b, uint32_t& hi, uint32_t& lo)
{
    __nv_bfloat16 ha = __float2bfloat16(a), hb = __float2bfloat16(b);
    __nv_bfloat16 la = __float2bfloat16(a - __bfloat162float(ha));
    __nv_bfloat16 lb = __float2bfloat16(b - __bfloat162float(hb));
    hi = ((uint32_t)__bfloat16_as_ushort(hb) << 16) | (uint32_t)__bfloat16_as_ushort(ha);
    lo = ((uint32_t)__bfloat16_as_ushort(lb) << 16) | (uint32_t)__bfloat16_as_ushort(la);
}

// ---------------------------------------------------------------------------
// Merged conversion kernel (unchanged from round 13)
// ---------------------------------------------------------------------------
#define NB_X  3072
#define NB_WQ 1728
#define NB_WO 576
#define NB_ALL (NB_X + NB_WQ + NB_WO)

__device__ __forceinline__ void splitT_tile(
    const float* __restrict__ in, __nv_bfloat16* __restrict__ hiT,
    __nv_bfloat16* __restrict__ loT, int K, int N, int k0, int n0,
    int tid, float (*t)[33])
{
    const int tx = tid & 31, ty = tid >> 5;
    #pragma unroll
    for (int i = 0; i < 32; i += 8)
        t[ty + i][tx] = in[(size_t)(k0 + ty + i) * N + n0 + tx];
    __syncthreads();
    #pragma unroll
    for (int i = 0; i < 32; i += 8) {
        float v = t[tx][ty + i];
        __nv_bfloat16 h = __float2bfloat16(v);
        size_t o = (size_t)(n0 + ty + i) * K + k0 + tx;
        hiT[o] = h;
        loT[o] = __float2bfloat16(v - __bfloat162float(h));
    }
}

__global__ __launch_bounds__(256) void conv_all_kernel(
    const float* __restrict__ x, const float* __restrict__ Wqkv,
    const float* __restrict__ Wo,
    __nv_bfloat16* __restrict__ xhi, __nv_bfloat16* __restrict__ xlo,
    __nv_bfloat16* __restrict__ wqh, __nv_bfloat16* __restrict__ wql,
    __nv_bfloat16* __restrict__ woh, __nv_bfloat16* __restrict__ wol)
{
    __shared__ float t[32][33];
    const int bid = blockIdx.x, tid = threadIdx.x;

    if (bid < NB_X) {
        const int gid = bid * 256 + tid;
        float4 v = ((const float4*)x)[gid];
        uint2 hi, lo;
        split2(v.x, v.y, hi.x, lo.x);
        split2(v.z, v.w, hi.y, lo.y);
        ((uint2*)xhi)[gid] = hi;
        ((uint2*)xlo)[gid] = lo;
    } else if (bid < NB_X + NB_WQ) {
        const int b2 = bid - NB_X;
        const int n0 = (b2 % 72) * 32, k0 = (b2 / 72) * 32;
        splitT_tile(Wqkv, wqh, wql, DD, 3 * DD, k0, n0, tid, t);
    } else {
        const int b3 = bid - NB_X - NB_WQ;
        const int n0 = (b3 % 24) * 32, k0 = (b3 / 24) * 32;
        splitT_tile(Wo, woh, wol, DD, DD, k0, n0, tid, t);
    }
}

// ---------------------------------------------------------------------------
// bf16x3 mma.sync GEMM: 3-stage ring, ONE barrier/iter, depth-2 prefetch.
// Combined hi|lo tiles: row = [32 hi bf16 | 32 lo bf16] = 128B data + 16 pad,
// SMS=72 (144B stride, ldmatrix conflict-free: 16r mod 128 covers all 8 quads).
// Stage = A tile + B tile = 36864B; 3 stages = 108KB -> 2 CTAs/SM.
// BK=32 work per barrier (proven R7 amount).
// FIXED vs R14: staging now covers all 8 16B-chunks per row (u in 0..7;
// u<4 -> hi bytes [0,64), u>=4 -> lo bytes [64,128)).
// ---------------------------------------------------------------------------
#define SMS 72
#define TILE_BYTES (128 * SMS * 2)              // 18432
#define STAGE_BYTES (2 * TILE_BYTES)            // 36864 (A, B)
#define GEMM_SMEM (3 * STAGE_BYTES)             // 110592

__global__ __launch_bounds__(256) void gemm_bf16x3_kernel(
    const __nv_bfloat16* __restrict__ Ahi, const __nv_bfloat16* __restrict__ Alo,
    const __nv_bfloat16* __restrict__ Bthi, const __nv_bfloat16* __restrict__ Btlo,
    float* __restrict__ C, int M, int N, int K)
{
    extern __shared__ __align__(128) char smem[];
    const uint32_t smem_base = smem_u32(smem);

    const int tid = threadIdx.x;
    const int wid = tid >> 5, lane = tid & 31;
    const int g = lane >> 2, tg = lane & 3;
    const int wm = wid >> 2, wn = wid & 3;        // 2 x 4 warp grid
    const int mbase = wm * 64, nbase = wn * 32;
    const int bm = blockIdx.y * 128, bn = blockIdx.x * 128;

    const __nv_bfloat16* Ah = Ahi + (size_t)bm * K;
    const __nv_bfloat16* Al = Alo + (size_t)bm * K;
    const __nv_bfloat16* Bh = Bthi + (size_t)bn * K;
    const __nv_bfloat16* Bl = Btlo + (size_t)bn * K;

    const int niter = K >> 5;

    // staging coords: per tile 1024 chunks of 16B (128 rows x 8), 4/thread/tile
    // chunk c: row = c>>3, u = c&7; u<4 -> hi half [0,64), u>=4 -> lo [64,128)
    uint32_t std_[4];
    int ssrc[4];
    bool shi[4];
    #pragma unroll
    for (int i = 0; i < 4; i++) {
        const int c = tid + 256 * i;
        const int r = c >> 3, u = c & 7;
        std_[i] = (uint32_t)(r * (SMS * 2) + u * 16);
        ssrc[i] = r * K + (u & 3) * 8;
        shi[i] = (u < 4);
    }

    // ldmatrix lane address components (within a tile; lo half = +64B)
    const uint32_t a_lane = (uint32_t)((lane & 15) * (SMS * 2) + ((lane >> 4) << 4));
    const uint32_t b_lane = (uint32_t)((lane & 7) * (SMS * 2) + (((lane >> 3) & 1) << 4));

    float acc[4][4][4];
    #pragma unroll
    for (int i = 0; i < 4; i++)
        #pragma unroll
        for (int j = 0; j < 4; j++)
            #pragma unroll
            for (int c = 0; c < 4; c++) acc[i][j][c] = 0.f;

    // ---- prologue: prefetch stages 0, 1 ----
    #pragma unroll
    for (int p = 0; p < 2; p++) {
        const uint32_t sb = smem_base + (uint32_t)p * STAGE_BYTES;
        const int k0 = p << 5;
        #pragma unroll
        for (int i = 0; i < 4; i++) {
            cp_async16(sb + std_[i], (shi[i] ? Ah : Al) + ssrc[i] + k0);
            cp_async16(sb + TILE_BYTES + std_[i], (shi[i] ? Bh : Bl) + ssrc[i] + k0);
        }
        CP_COMMIT();
    }

    int bufi = 0;        // it % 3
    int wbufi = 2;       // (it+2) % 3
    for (int it = 0; it < niter; it++) {
        CP_WAIT1();
        __syncthreads();

        const uint32_t sbuf = smem_base + (uint32_t)bufi * STAGE_BYTES;

        #pragma unroll
        for (int kk = 0; kk < 32; kk += 16) {
            uint32_t ah[4][4], al[4][4], bh[4][2], bl[4][2];
            #pragma unroll
            for (int mt = 0; mt < 4; mt++) {
                const uint32_t ro = sbuf + a_lane +
                    (uint32_t)((mbase + mt * 16) * (SMS * 2) + kk * 2);
                LDSM_X4(ah[mt][0], ah[mt][1], ah[mt][2], ah[mt][3], ro);
                LDSM_X4(al[mt][0], al[mt][1], al[mt][2], al[mt][3], ro + 64);
            }
            #pragma unroll
            for (int nt = 0; nt < 4; nt++) {
                const uint32_t ro = sbuf + TILE_BYTES + b_lane +
                    (uint32_t)((nbase + nt * 8) * (SMS * 2) + kk * 2);
                LDSM_X2(bh[nt][0], bh[nt][1], ro);
                LDSM_X2(bl[nt][0], bl[nt][1], ro + 64);
            }
            #pragma unroll
            for (int mt = 0; mt < 4; mt++)
                #pragma unroll
                for (int nt = 0; nt < 4; nt++)
                    mma16816(acc[mt][nt], ah[mt], bh[nt]);
            #pragma unroll
            for (int mt = 0; mt < 4; mt++)
                #pragma unroll
                for (int nt = 0; nt < 4; nt++)
                    mma16816(acc[mt][nt], ah[mt], bl[nt]);
            #pragma unroll
            for (int mt = 0; mt < 4; mt++)
                #pragma unroll
                for (int nt = 0; nt < 4; nt++)
                    mma16816(acc[mt][nt], al[mt], bh[nt]);
        }

        // issue stage it+2 into buffer (it-1)%3 (drained by this iter's barrier)
        const int nx = it + 2;
        if (nx < niter) {
            const uint32_t db = smem_base + (uint32_t)wbufi * STAGE_BYTES;
            const int k0 = nx << 5;
            #pragma unroll
            for (int i = 0; i < 4; i++) {
                cp_async16(db + std_[i], (shi[i] ? Ah : Al) + ssrc[i] + k0);
                cp_async16(db + TILE_BYTES + std_[i], (shi[i] ? Bh : Bl) + ssrc[i] + k0);
            }
        }
        CP_COMMIT();

        bufi = (bufi == 2) ? 0 : bufi + 1;
        wbufi = (wbufi == 2) ? 0 : wbufi + 1;
    }

    // Epilogue: direct fp32 stores
    #pragma unroll
    for (int mt = 0; mt < 4; mt++) {
        #pragma unroll
        for (int nt = 0; nt < 4; nt++) {
            const int row = bm + mbase + mt * 16 + g;
            const int col = bn + nbase + nt * 8 + tg * 2;
            float2 v0; v0.x = acc[mt][nt][0]; v0.y = acc[mt][nt][1];
            float2 v1; v1.x = acc[mt][nt][2]; v1.y = acc[mt][nt][3];
            *(float2*)&C[(size_t)row * N + col] = v0;
            *(float2*)&C[(size_t)(row + 8) * N + col] = v1;
        }
    }
}

// ---------------------------------------------------------------------------
// Tensor-core sliding-window attention (bf16x3), fused output split.
// (exact round-7/13 version)
// ---------------------------------------------------------------------------
#define AT_KH 0
#define AT_KL 24576
#define AT_VH 49152
#define AT_VL 73728
#define AT_PN 98304
#define AT_RM 99072
#define AT_RS 99584
#define ATTN_SMEM 100096

__global__ __launch_bounds__(256, 2) void attn_mma_kernel(
    const float* __restrict__ qkv, const float* __restrict__ pmask,
    __nv_bfloat16* __restrict__ ohi, __nv_bfloat16* __restrict__ olo)
{
    extern __shared__ __align__(128) char smem[];
    const uint32_t sb = smem_u32(smem);
    float* PNf = (float*)(smem + AT_PN);
    float* RMf = (float*)(smem + AT_RM);
    float* RSf = (float*)(smem + AT_RS);

    const int qt = blockIdx.x, h = blockIdx.y, b = blockIdx.z;
    const int q0 = qt * 64;
    const int kstart = q0 - 64;
    const int tid = threadIdx.x;
    const int wid = tid >> 5, lane = tid & 31;
    const int g = lane >> 2, tg = lane & 3;

    const int wm1 = wid >> 1, wn1 = wid & 1;
    uint32_t qh[4][4], ql[4][4];
    {
        const float* qr0 = qkv + ((size_t)(b * SS + q0 + wm1 * 16 + g)) * (3 * DD) + h * HDIM;
        const float* qr8 = qr0 + (size_t)8 * (3 * DD);
        #pragma unroll
        for (int ks = 0; ks < 4; ks++) {
            float2 x0 = *(const float2*)(qr0 + ks * 16 + tg * 2);
            float2 x1 = *(const float2*)(qr8 + ks * 16 + tg * 2);
            float2 x2 = *(const float2*)(qr0 + ks * 16 + 8 + tg * 2);
            float2 x3 = *(const float2*)(qr8 + ks * 16 + 8 + tg * 2);
            split2(x0.x, x0.y, qh[ks][0], ql[ks][0]);
            split2(x1.x, x1.y, qh[ks][1], ql[ks][1]);
            split2(x2.x, x2.y, qh[ks][2], ql[ks][2]);
            split2(x3.x, x3.y, qh[ks][3], ql[ks][3]);
        }
    }

    for (int idx = tid; idx < 192 * 8; idx += 256) {
        const int key = idx >> 3, u = idx & 7;
        const int gk = kstart + key;
        float4 kv0, kv1, vv0, vv1;
        if (gk >= 0 && gk < SS) {
            const float* base = qkv + ((size_t)(b * SS + gk)) * (3 * DD) + h * HDIM + u * 8;
            kv0 = *(const float4*)(base + DD);
            kv1 = *(const float4*)(base + DD + 4);
            vv0 = *(const float4*)(base + 2 * DD);
            vv1 = *(const float4*)(base + 2 * DD + 4);
        } else {
            kv0 = kv1 = vv0 = vv1 = make_float4(0.f, 0.f, 0.f, 0.f);
        }
        const uint32_t swo = (uint32_t)(key * 128 + ((u * 16) ^ ((key & 7) << 4)));
        uint4 hi4, lo4;
        split2(kv0.x, kv0.y, hi4.x, lo4.x);
        split2(kv0.z, kv0.w, hi4.y, lo4.y);
        split2(kv1.x, kv1.y, hi4.z, lo4.z);
        split2(kv1.z, kv1.w, hi4.w, lo4.w);
        *(uint4*)(smem + AT_KH + swo) = hi4;
        *(uint4*)(smem + AT_KL + swo) = lo4;
        split2(vv0.x, vv0.y, hi4.x, lo4.x);
        split2(vv0.z, vv0.w, hi4.y, lo4.y);
        split2(vv1.x, vv1.y, hi4.z, lo4.z);
        split2(vv1.z, vv1.w, hi4.w, lo4.w);
        *(uint4*)(smem + AT_VH + swo) = hi4;
        *(uint4*)(smem + AT_VL + swo) = lo4;
    }
    for (int j = tid; j < 192; j += 256) {
        const int gk = kstart + j;
        PNf[j] = (gk >= 0 && gk < SS) ? (1.0f - pmask[b * SS + gk]) * NEGV : -1e30f;
    }
    __syncthreads();

    float acc[12][4];
    #pragma unroll
    for (int nt = 0; nt < 12; nt++)
        #pragma unroll
        for (int c = 0; c < 4; c++) acc[nt][c] = 0.f;

    #pragma unroll
    for (int ks = 0; ks < 4; ks++) {
        #pragma unroll
        for (int nt = 0; nt < 12; nt++) {
            const int brow = wn1 * 96 + nt * 8 + (lane & 7);
            const uint32_t bo = (uint32_t)(brow * 128 +
                ((ks * 32 + ((lane >> 3) & 1) * 16) ^ ((lane & 7) << 4)));
            uint32_t bh[2], bl[2];
            LDSM_X2(bh[0], bh[1], sb + AT_KH + bo);
            LDSM_X2(bl[0], bl[1], sb + AT_KL + bo);
            mma16816(acc[nt], qh[ks], bh);
            mma16816(acc[nt], qh[ks], bl);
            mma16816(acc[nt], ql[ks], bh);
        }
    }

    const int r0 = wm1 * 16 + g;
    const int r1 = r0 + 8;
    #pragma unroll
    for (int nt = 0; nt < 12; nt++) {
        const int j0 = wn1 * 96 + nt * 8 + tg * 2;
        #pragma unroll
        for (int e = 0; e < 4; e++) {
            const int j = j0 + (e & 1);
            const int rr = (e < 2) ? r0 : r1;
            const int diff = j - rr;
            acc[nt][e] = (diff >= 0 && diff <= 128)
                       ? acc[nt][e] * 0.125f + PNf[j] : -1e30f;
        }
    }

    float m0 = -1e30f, m1 = -1e30f;
    #pragma unroll
    for (int nt = 0; nt < 12; nt++) {
        m0 = fmaxf(m0, fmaxf(acc[nt][0], acc[nt][1]));
        m1 = fmaxf(m1, fmaxf(acc[nt][2], acc[nt][3]));
    }
    #pragma unroll
    for (int o = 1; o <= 2; o <<= 1) {
        m0 = fmaxf(m0, __shfl_xor_sync(0xffffffffu, m0, o));
        m1 = fmaxf(m1, __shfl_xor_sync(0xffffffffu, m1, o));
    }
    if (tg == 0) { RMf[r0 * 2 + wn1] = m0; RMf[r1 * 2 + wn1] = m1; }
    __syncthreads();
    m0 = fmaxf(RMf[r0 * 2], RMf[r0 * 2 + 1]);
    m1 = fmaxf(RMf[r1 * 2], RMf[r1 * 2 + 1]);

    float s0 = 0.f, s1 = 0.f;
    #pragma unroll
    for (int nt = 0; nt < 12; nt++) {
        acc[nt][0] = __expf(acc[nt][0] - m0);
        acc[nt][1] = __expf(acc[nt][1] - m0);
        acc[nt][2] = __expf(acc[nt][2] - m1);
        acc[nt][3] = __expf(acc[nt][3] - m1);
        s0 += acc[nt][0] + acc[nt][1];
        s1 += acc[nt][2] + acc[nt][3];
    }
    #pragma unroll
    for (int o = 1; o <= 2; o <<= 1) {
        s0 += __shfl_xor_sync(0xffffffffu, s0, o);
        s1 += __shfl_xor_sync(0xffffffffu, s1, o);
    }
    if (tg == 0) { RSf[r0 * 2 + wn1] = s0; RSf[r1 * 2 + wn1] = s1; }
    __syncthreads();
    const float inv0 = 1.f / (RSf[r0 * 2] + RSf[r0 * 2 + 1]);
    const float inv1 = 1.f / (RSf[r1 * 2] + RSf[r1 * 2 + 1]);

    #pragma unroll
    for (int nt = 0; nt < 12; nt++) {
        const int j0 = wn1 * 96 + nt * 8 + tg * 2;
        uint32_t hi, lo;
        split2(acc[nt][0] * inv0, acc[nt][1] * inv0, hi, lo);
        uint32_t o0 = (uint32_t)(r0 * 384 + ((j0 * 2) ^ ((r0 & 7) << 4)));
        *(uint32_t*)(smem + AT_KH + o0) = hi;
        *(uint32_t*)(smem + AT_KL + o0) = lo;
        split2(acc[nt][2] * inv1, acc[nt][3] * inv1, hi, lo);
        uint32_t o1 = (uint32_t)(r1 * 384 + ((j0 * 2) ^ ((r1 & 7) << 4)));
        *(uint32_t*)(smem + AT_KH + o1) = hi;
        *(uint32_t*)(smem + AT_KL + o1) = lo;
    }
    __syncthreads();

    const int wm3 = wm1, wn3 = wn1;
    float oacc[4][4];
    #pragma unroll
    for (int nt = 0; nt < 4; nt++)
        #pragma unroll
        for (int c = 0; c < 4; c++) oacc[nt][c] = 0.f;

    #pragma unroll
    for (int ks = 0; ks < 12; ks++) {
        const int prow = wm3 * 16 + (lane & 15);
        const uint32_t po = (uint32_t)(prow * 384 +
            ((ks * 32 + (lane >> 4) * 16) ^ ((prow & 7) << 4)));
        uint32_t ph[4], pl[4];
        LDSM_X4(ph[0], ph[1], ph[2], ph[3], sb + AT_KH + po);
        LDSM_X4(pl[0], pl[1], pl[2], pl[3], sb + AT_KL + po);
        #pragma unroll
        for (int nt = 0; nt < 4; nt++) {
            const int vrow = ks * 16 + (lane & 15);
            const uint32_t vo = (uint32_t)(vrow * 128 +
                (((wn3 * 32 + nt * 8) * 2) ^ ((vrow & 7) << 4)));
            uint32_t vh[2], vl[2];
            LDSM_X2T(vh[0], vh[1], sb + AT_VH + vo);
            LDSM_X2T(vl[0], vl[1], sb + AT_VL + vo);
            mma16816(oacc[nt], ph, vh);
            mma16816(oacc[nt], ph, vl);
            mma16816(oacc[nt], pl, vh);
        }
    }

    #pragma unroll
    for (int nt = 0; nt < 4; nt++) {
        const int gq0 = q0 + wm3 * 16 + g;
        const int col = h * HDIM + wn3 * 32 + nt * 8 + tg * 2;
        uint32_t hi, lo;
        size_t off = ((size_t)(b * SS + gq0)) * DD + col;
        split2(oacc[nt][0], oacc[nt][1], hi, lo);
        *(uint32_t*)(ohi + off) = hi;
        *(uint32_t*)(olo + off) = lo;
        off += (size_t)8 * DD;
        split2(oacc[nt][2], oacc[nt][3], hi, lo);
        *(uint32_t*)(ohi + off) = hi;
        *(uint32_t*)(olo + off) = lo;
    }
}

// ---------------------------------------------------------------------------
extern "C" void kernel_launch(void* const* d_in, const int* in_sizes, int n_in,
                              void* d_out, int out_size)
{
    const float* x    = (const float*)d_in[0];
    const float* pm   = (const float*)d_in[1];
    const float* Wqkv = (const float*)d_in[2];
    const float* Wo   = (const float*)d_in[3];
    float* out = (float*)d_out;

    float* qkv_p;
    __nv_bfloat16 *xhi, *xlo, *wqh, *wql, *woh, *wol, *ahi, *alo;
    cudaGetSymbolAddress((void**)&qkv_p, g_qkv);
    cudaGetSymbolAddress((void**)&xhi, g_xhi);
    cudaGetSymbolAddress((void**)&xlo, g_xlo);
    cudaGetSymbolAddress((void**)&wqh, g_wqh);
    cudaGetSymbolAddress((void**)&wql, g_wql);
    cudaGetSymbolAddress((void**)&woh, g_woh);
    cudaGetSymbolAddress((void**)&wol, g_wol);
    cudaGetSymbolAddress((void**)&ahi, g_ahi);
    cudaGetSymbolAddress((void**)&alo, g_alo);

    const int M = BB * SS;            // 4096

    static bool attr_done = false;
    if (!attr_done) {
        cudaFuncSetAttribute(gemm_bf16x3_kernel,
                             cudaFuncAttributeMaxDynamicSharedMemorySize, GEMM_SMEM);
        cudaFuncSetAttribute(attn_mma_kernel,
                             cudaFuncAttributeMaxDynamicSharedMemorySize, ATTN_SMEM);
        attr_done = true;
    }

    // 0) All input conversions in one launch
    conv_all_kernel<<<NB_ALL, 256>>>(x, Wqkv, Wo, xhi, xlo, wqh, wql, woh, wol);

    // 1) QKV projection (tensor cores)
    gemm_bf16x3_kernel<<<dim3(3 * DD / 128, M / 128), 256, GEMM_SMEM>>>(
        xhi, xlo, wqh, wql, qkv_p, M, 3 * DD, DD);

    // 2) Sliding-window attention (tensor cores), writes bf16 hi/lo directly
    attn_mma_kernel<<<dim3(SS / 64, HH, BB), 256, ATTN_SMEM>>>(qkv_p, pm, ahi, alo);

    // 3) Output projection (tensor cores)
    gemm_bf16x3_kernel<<<dim3(DD / 128, M / 128), 256, GEMM_SMEM>>>(
        ahi, alo, woh, wol, out, M, DD, DD);
}